// round 8
// baseline (speedup 1.0000x reference)
#include <cuda_runtime.h>

// Fixed-point reachability from node 0 over (left, right) child edges.
// Reference runs N=8192 relaxation steps; result == transitive closure of {0},
// computed by BFS-until-converged in ONE CTA:
//   - runtime input identification: the two int arrays with all values in
//     [-1, N) are the child arrays (float32 thresholds reinterpreted as int32
//     are ~ +/-1e9, never in range) -> immune to metadata input ordering
//   - 8192-bit reachability mask in shared memory (256 x u32)
//   - children cached in registers (8 nodes per thread, coalesced load)
//   - each node expanded exactly once (per-thread done bitmask)
//   - OUTPUT IS FLOAT32 (bool ref cast by the dataset): write 0.0f / 1.0f

#define NNODES      8192
#define NTHREADS    1024
#define PER_THREAD  (NNODES / NTHREADS)   // 8
#define NWORDS      (NNODES / 32)         // 256

__global__ __launch_bounds__(NTHREADS, 1)
void DAGGenome_reach_kernel(const int* __restrict__ a0,
                            const int* __restrict__ a1,
                            const int* __restrict__ a2,
                            float* __restrict__ out)
{
    __shared__ unsigned int reach[NWORDS];
    __shared__ int changed;
    __shared__ int validf[3];

    const int tid = threadIdx.x;
    const int* arrs[3] = { a0, a1, a2 };

    // --- init ---
    if (tid < 3) validf[tid] = 1;
    #pragma unroll
    for (int w = tid; w < NWORDS; w += NTHREADS) reach[w] = 0u;
    __syncthreads();

    // --- identify which inputs are genuine child arrays ---
    #pragma unroll
    for (int k = 0; k < 3; k++) {
        const int* p = arrs[k];
        bool ok = true;
        #pragma unroll
        for (int j = 0; j < PER_THREAD; j++) {
            const int v = p[j * NTHREADS + tid];
            ok = ok && (v >= -1) && (v < NNODES);
        }
        if (!ok) validf[k] = 0;   // benign race: only 1 -> 0 transitions
    }
    __syncthreads();

    int li, ri;
    if (validf[1] && validf[2]) {            // expected metadata order
        li = 1; ri = 2;
    } else {                                  // pick the two valid arrays
        li = -1; ri = -1;
        #pragma unroll
        for (int k = 0; k < 3; k++) {
            if (validf[k]) { if (li < 0) li = k; else if (ri < 0) ri = k; }
        }
        if (li < 0) li = 1;                   // degenerate fallbacks
        if (ri < 0) ri = li;
    }
    const int* __restrict__ lp = arrs[li];
    const int* __restrict__ rp = arrs[ri];

    // seed: node 0 reachable
    if (tid == 0) reach[0] = 1u;

    // cache this thread's nodes' children in registers (coalesced)
    int lc[PER_THREAD], rc[PER_THREAD];
    #pragma unroll
    for (int j = 0; j < PER_THREAD; j++) {
        const int i = j * NTHREADS + tid;
        lc[j] = lp[i];
        rc[j] = rp[i];
    }

    unsigned int done = 0;   // bit j: node (j*1024+tid) already expanded
    __syncthreads();

    // --- BFS to fixed point ---
    for (;;) {
        if (tid == 0) changed = 0;
        __syncthreads();

        #pragma unroll
        for (int j = 0; j < PER_THREAD; j++) {
            if (done & (1u << j)) continue;
            const int i = j * NTHREADS + tid;
            if (reach[i >> 5] & (1u << (i & 31))) {
                done |= (1u << j);
                const int a = lc[j];
                if (a >= 0) {
                    const unsigned int bit = 1u << (a & 31);
                    const unsigned int old = atomicOr(&reach[a >> 5], bit);
                    if (!(old & bit)) changed = 1;
                }
                const int b = rc[j];
                if (b >= 0) {
                    const unsigned int bit = 1u << (b & 31);
                    const unsigned int old = atomicOr(&reach[b >> 5], bit);
                    if (!(old & bit)) changed = 1;
                }
            }
        }

        __syncthreads();
        if (changed == 0) break;
        __syncthreads();   // keep the read above from racing the next reset
    }

    // --- write float32 output (d_out poisoned; write every element) ---
    #pragma unroll
    for (int j = 0; j < PER_THREAD; j++) {
        const int i = j * NTHREADS + tid;
        out[i] = (reach[i >> 5] >> (i & 31)) & 1u ? 1.0f : 0.0f;
    }
}

extern "C" void kernel_launch(void* const* d_in, const int* in_sizes, int n_in,
                              void* d_out, int out_size)
{
    const int* a0 = (const int*)d_in[0];
    const int* a1 = (const int*)d_in[1];
    const int* a2 = (const int*)d_in[2];
    float* out = (float*)d_out;

    DAGGenome_reach_kernel<<<1, NTHREADS>>>(a0, a1, a2, out);
}

// round 9
// speedup vs baseline: 1.1234x; 1.1234x over previous
#include <cuda_runtime.h>

// Transitive closure of {0} under (left, right) edges == reference's 8192-step
// fixed point. BFS-until-converged in ONE CTA, tuned for iteration latency:
//   - thread tid owns nodes [8*tid, 8*tid+8): its 8 reach bits are ONE BYTE of
//     one shared word -> 1 LDS per iteration (was 8)
//   - 1 __syncthreads per iteration via iteration-indexed changed-flag array
//     (pre-zeroed; rolling reset for wraparound safety)
//   - 2 relaxation sweeps between barriers (smem atomics visible immediately)
//   - children in registers via int4 loads; each node expanded exactly once
//   - input order confirmed in R8: d_in[1]=left, d_in[2]=right; output float32

#define NNODES    8192
#define NTHREADS  1024
#define NWORDS    (NNODES / 32)    // 256
#define CHG_SLOTS 2048             // >= any possible depth window; rolling reset

__global__ __launch_bounds__(NTHREADS, 1)
void DAGGenome_reach_kernel(const int* __restrict__ left,
                            const int* __restrict__ right,
                            float* __restrict__ out)
{
    __shared__ unsigned int reach[NWORDS];
    __shared__ int chg[CHG_SLOTS];

    const int tid = threadIdx.x;

    // init: mask + flag slots
    #pragma unroll
    for (int w = tid; w < NWORDS; w += NTHREADS) reach[w] = 0u;
    #pragma unroll
    for (int w = tid; w < CHG_SLOTS; w += NTHREADS) chg[w] = 0;
    if (tid == 0) reach[0] = 1u;   // seed node 0

    // children of my 8 consecutive nodes, fully coalesced int4 loads
    const int4* lp = (const int4*)left  + tid * 2;
    const int4* rp = (const int4*)right + tid * 2;
    const int4 l0 = lp[0], l1 = lp[1];
    const int4 r0 = rp[0], r1 = rp[1];
    const int lc[8] = { l0.x, l0.y, l0.z, l0.w, l1.x, l1.y, l1.z, l1.w };
    const int rc[8] = { r0.x, r0.y, r0.z, r0.w, r1.x, r1.y, r1.z, r1.w };

    const int word  = tid >> 2;        // my reach word
    const int shift = (tid & 3) * 8;   // my byte within it
    unsigned int done = 0;             // bit j: node 8*tid+j already expanded

    __syncthreads();

    // --- BFS to fixed point: ONE barrier per iteration ---
    for (int t = 0; ; t++) {
        bool local_changed = false;

        #pragma unroll 1
        for (int sweep = 0; sweep < 2; sweep++) {
            const unsigned int pending =
                ((reach[word] >> shift) & 0xffu) & ~done;
            if (pending) {
                done |= pending;
                #pragma unroll
                for (int j = 0; j < 8; j++) {
                    if (pending & (1u << j)) {
                        const int a = lc[j];
                        if (a >= 0) {
                            const unsigned int bit = 1u << (a & 31);
                            const unsigned int old = atomicOr(&reach[a >> 5], bit);
                            if (!(old & bit)) local_changed = true;
                        }
                        const int b = rc[j];
                        if (b >= 0) {
                            const unsigned int bit = 1u << (b & 31);
                            const unsigned int old = atomicOr(&reach[b >> 5], bit);
                            if (!(old & bit)) local_changed = true;
                        }
                    }
                }
            }
        }

        const int slot = t & (CHG_SLOTS - 1);
        if (local_changed) chg[slot] = 1;                        // benign race
        if (tid == 0) chg[(t + CHG_SLOTS / 2) & (CHG_SLOTS - 1)] = 0; // rolling reset
        __syncthreads();
        if (!chg[slot]) break;
        // next iteration uses slot t+1: no reset/read race, no extra barrier
    }

    // --- write float32 output: my byte -> 8 floats, 2x float4 stores ---
    const unsigned int myb = (reach[word] >> shift) & 0xffu;
    float4 o0, o1;
    o0.x = (myb & 0x01u) ? 1.0f : 0.0f;
    o0.y = (myb & 0x02u) ? 1.0f : 0.0f;
    o0.z = (myb & 0x04u) ? 1.0f : 0.0f;
    o0.w = (myb & 0x08u) ? 1.0f : 0.0f;
    o1.x = (myb & 0x10u) ? 1.0f : 0.0f;
    o1.y = (myb & 0x20u) ? 1.0f : 0.0f;
    o1.z = (myb & 0x40u) ? 1.0f : 0.0f;
    o1.w = (myb & 0x80u) ? 1.0f : 0.0f;
    float4* op = (float4*)out + tid * 2;
    op[0] = o0;
    op[1] = o1;
}

extern "C" void kernel_launch(void* const* d_in, const int* in_sizes, int n_in,
                              void* d_out, int out_size)
{
    const int* left  = (const int*)d_in[1];
    const int* right = (const int*)d_in[2];
    float* out = (float*)d_out;

    DAGGenome_reach_kernel<<<1, NTHREADS>>>(left, right, out);
}

// round 10
// speedup vs baseline: 1.5000x; 1.3352x over previous
#include <cuda_runtime.h>

// Transitive closure of {0} under (left,right) == reference's 8192-step fixed
// point. One-CTA BFS-until-converged, ATOMIC-FREE:
//   - byte-per-node reachability map in smem (8 KB): "set reachable" is a
//     plain STS of constant 1 (racing writers store the same value -> no RMW).
//     R9 was pinned to the ATOMS 2cyc/lane LSU floor (~30k cyc); this removes it.
//   - owner-side change detection: a byte flip in round t creates a new
//     pending bit whose owner flags 'changed' in round t -> exact termination,
//     zero per-child loads.
//   - thread tid owns nodes [8*tid, 8*tid+8): one 8-byte LDS per sweep,
//     byte->bitmask via multiply-compress; 3 sweeps per barrier.
//   - children in registers (int4 loads); expand-once 'done' mask;
//     1 barrier/round via iteration-indexed flag slots with rolling reset.

#define NNODES    8192
#define NTHREADS  1024
#define CHG_SLOTS 64
#define SWEEPS    3

__global__ __launch_bounds__(NTHREADS, 1)
void DAGGenome_reach_kernel(const int* __restrict__ left,
                            const int* __restrict__ right,
                            float* __restrict__ out)
{
    __shared__ __align__(16) unsigned char reach8[NNODES];
    __shared__ int chg[CHG_SLOTS];

    const int tid = threadIdx.x;

    // init: zero mask (1 u64 store per thread) + flag slots
    ((unsigned long long*)reach8)[tid] = 0ull;
    if (tid < CHG_SLOTS) chg[tid] = 0;
    if (tid == 0) reach8[0] = 1;          // same thread zeroed slot 0: ordered

    // children of my 8 consecutive nodes (coalesced int4 loads)
    const int4* lp = (const int4*)left  + tid * 2;
    const int4* rp = (const int4*)right + tid * 2;
    const int4 l0 = lp[0], l1 = lp[1];
    const int4 r0 = rp[0], r1 = rp[1];
    const int lc[8] = { l0.x, l0.y, l0.z, l0.w, l1.x, l1.y, l1.z, l1.w };
    const int rc[8] = { r0.x, r0.y, r0.z, r0.w, r1.x, r1.y, r1.z, r1.w };

    volatile unsigned long long* vmy =
        (volatile unsigned long long*)reach8 + tid;     // my 8 bytes
    volatile unsigned char* vr = (volatile unsigned char*)reach8;

    unsigned int done = 0;   // bit j: node 8*tid+j already expanded
    __syncthreads();

    // --- BFS to fixed point: one barrier per round ---
    for (int t = 0; ; t++) {
        bool local_changed = false;

        #pragma unroll 1
        for (int s = 0; s < SWEEPS; s++) {
            const unsigned long long v = *vmy;          // re-read each sweep
            const unsigned int lo = (unsigned int)v;
            const unsigned int hi = (unsigned int)(v >> 32);
            // bytes (0/1) -> 8-bit mask
            const unsigned int got = ((lo * 0x01020408u) >> 24)
                                   | (((hi * 0x01020408u) >> 24) << 4);
            const unsigned int pending = got & ~done;
            if (pending) {
                local_changed = true;
                done |= pending;
                #pragma unroll
                for (int j = 0; j < 8; j++) {
                    if (pending & (1u << j)) {
                        const int a = lc[j];
                        if (a >= 0) vr[a] = 1;          // plain STS, race-free
                        const int b = rc[j];
                        if (b >= 0) vr[b] = 1;
                    }
                }
            }
        }

        const int slot = t & (CHG_SLOTS - 1);
        if (local_changed) chg[slot] = 1;                       // benign race
        if (tid == 0) chg[(t + CHG_SLOTS / 2) & (CHG_SLOTS - 1)] = 0;
        __syncthreads();
        if (!chg[slot]) break;
    }

    // --- float32 output: my 8 bytes -> 2x float4 stores ---
    const unsigned long long v = *vmy;
    float4 o0, o1;
    o0.x = (v & 0x01ull)         ? 1.0f : 0.0f;
    o0.y = (v & (1ull << 8))     ? 1.0f : 0.0f;
    o0.z = (v & (1ull << 16))    ? 1.0f : 0.0f;
    o0.w = (v & (1ull << 24))    ? 1.0f : 0.0f;
    o1.x = (v & (1ull << 32))    ? 1.0f : 0.0f;
    o1.y = (v & (1ull << 40))    ? 1.0f : 0.0f;
    o1.z = (v & (1ull << 48))    ? 1.0f : 0.0f;
    o1.w = (v & (1ull << 56))    ? 1.0f : 0.0f;
    float4* op = (float4*)out + tid * 2;
    op[0] = o0;
    op[1] = o1;
}

extern "C" void kernel_launch(void* const* d_in, const int* in_sizes, int n_in,
                              void* d_out, int out_size)
{
    const int* left  = (const int*)d_in[1];
    const int* right = (const int*)d_in[2];
    float* out = (float*)d_out;

    DAGGenome_reach_kernel<<<1, NTHREADS>>>(left, right, out);
}